// round 16
// baseline (speedup 1.0000x reference)
#include <cuda_runtime.h>
#include <cuda_fp16.h>
#include <cstdint>

// ---------------------------------------------------------------------------
// Problem constants
// ---------------------------------------------------------------------------
#define BB 512      // batch
#define SS 256      // set size
#define DD 64       // feature dim (K)
#define HH 64       // n_hidden_sets
#define EE 8        // n_elements
#define HE 512      // H*E (N of GEMM)
#define BN_EPS 1e-5f

#define NCTA 148          // 1 CTA per SM (forced via smem); covers 148-SM part exactly
#define K1_THREADS 256
#define UNITS 1024        // 512 b x 2 halves (128 rows each)

// smem layout (bytes) — Phase C US overlays [0, ~69K) after Phase B retires
#define S_BUF0 0                    // X fp16 half-b buf 0 (16 KB)
#define S_BUF1 16384                // X fp16 half-b buf 1 (16 KB)
#define S_WFC  32768                // fc1_w transposed [h][j] (8 KB)
#define S_FB   40960                // fc1_b [32]
#define S_TSM  41088                // 64 floats (warp-0 private combine staging)
#define S_CTL  69632                // control ints (outside Phase C's US+PS)
// Request 120 KB so 2 CTAs cannot co-reside on one SM.
#define SM_TOTAL 122880

// ---------------------------------------------------------------------------
// Device scratch (no dynamic allocation allowed)
// ---------------------------------------------------------------------------
__device__ float g_part[UNITS * HH];   // per-(b,half) pooled partial sums
__device__ int   g_cnt[BB];            // half-arrival counters (self-resetting)
__device__ float g_u[BB * 32];         // fc1 output
__device__ int   g_done = 0;           // CTA completion counter

__device__ __forceinline__ uint32_t smem_u32(const void* p) {
    uint32_t a;
    asm("{ .reg .u64 t; cvta.to.shared.u64 t, %1; cvt.u32.u64 %0, t; }" : "=r"(a) : "l"(p));
    return a;
}
__device__ __forceinline__ uint32_t swz(uint32_t off) {   // SW128: conflict-free ldmatrix
    return off ^ ((off >> 3) & 0x70);
}
__device__ __forceinline__ float lrelu(float x) { return fmaxf(x, 0.01f * x); }

__device__ __forceinline__ void ldsm_x4(uint32_t addr, uint32_t& r0, uint32_t& r1,
                                        uint32_t& r2, uint32_t& r3) {
    asm volatile("ldmatrix.sync.aligned.m8n8.x4.shared.b16 {%0,%1,%2,%3}, [%4];"
                 : "=r"(r0), "=r"(r1), "=r"(r2), "=r"(r3) : "r"(addr));
}
__device__ __forceinline__ void mma_fp16(float& c0, float& c1, float& c2, float& c3,
                                         uint32_t a0, uint32_t a1, uint32_t a2, uint32_t a3,
                                         uint32_t b0, uint32_t b1) {
    asm volatile("mma.sync.aligned.m16n8k16.row.col.f32.f16.f16.f32 "
                 "{%0,%1,%2,%3}, {%4,%5,%6,%7}, {%8,%9}, {%0,%1,%2,%3};"
                 : "+f"(c0), "+f"(c1), "+f"(c2), "+f"(c3)
                 : "r"(a0), "r"(a1), "r"(a2), "r"(a3), "r"(b0), "r"(b1));
}
__device__ __forceinline__ uint32_t pack_h2(float lo, float hi) {
    __half2 h = __floats2half2_rn(lo, hi);
    return *(uint32_t*)&h;
}

// convert 4 float4 (one 64-row group's share) -> swizzled fp16 at bufoff
// (bufoff is 8192-aligned, so base + swz(local) == swz(base + local))
__device__ __forceinline__ void cvt_sts_group(char* smem, int bufoff, int tid,
                                              const float4* v) {
    #pragma unroll
    for (int j = 0; j < 4; j++) {
        int cc = tid + j * 256;            // float4 idx within 64-row group
        int row = cc >> 4, k4 = (cc & 15) << 2;
        uint32_t sw = swz((uint32_t)row * 128u + (uint32_t)k4 * 2u);
        *(uint2*)(smem + bufoff + sw) =
            make_uint2(pack_h2(v[j].x, v[j].y), pack_h2(v[j].z, v[j].w));
    }
}

// ---------------------------------------------------------------------------
// Single persistent kernel: 1 CTA/SM, static half-b schedule over 148 CTAs,
// double-buffered, ONE 8-warp barrier per unit, non-blocking cross-CTA combine.
// ---------------------------------------------------------------------------
__global__ __launch_bounds__(K1_THREADS, 1)
void fused_all(const float* __restrict__ X, const float* __restrict__ Wc,
               const float* __restrict__ fc1_w, const float* __restrict__ fc1_b,
               const float* __restrict__ gamma, const float* __restrict__ beta,
               const float* __restrict__ fc2_w, const float* __restrict__ fc2_b,
               float* __restrict__ out) {
    extern __shared__ char smem[];
    const uint32_t sb = smem_u32(smem);
    const int tid  = threadIdx.x;
    const int hb   = tid >> 5;        // warp id == h-block
    const int lane = tid & 31;
    int* ctl = (int*)(smem + S_CTL);  // [0]=last-CTA flag

    // ===== Phase A: stage fc1 weights/bias; B fragments direct from Wc =====
    for (int i = tid; i < 32 * HH; i += K1_THREADS) {
        int j = i >> 6, h = i & 63;
        ((float*)(smem + S_WFC))[h * 32 + j] = fc1_w[i];
    }
    if (tid < 32) ((float*)(smem + S_FB))[tid] = fc1_b[tid];

    // PTX m16n8k16 .col B mapping (bit-exact verified R11-R15):
    // bf[e][2*ks]  : k = ks*16 + (lane%4)*2 + {0,1},  n = e*64 + hb*8 + lane/4
    // bf[e][2*ks+1]: same with k+8
    uint32_t bf[EE][8];
    {
        const int n  = hb * 8 + (lane >> 2);
        const int kb = (lane & 3) * 2;
        #pragma unroll
        for (int e = 0; e < EE; e++) {
            const float* wc_n = Wc + e * 64 + n;
            #pragma unroll
            for (int ks = 0; ks < 4; ks++) {
                int k0 = ks * 16 + kb;
                bf[e][2 * ks]     = pack_h2(__ldg(wc_n + (size_t)k0 * HE),
                                            __ldg(wc_n + (size_t)(k0 + 1) * HE));
                bf[e][2 * ks + 1] = pack_h2(__ldg(wc_n + (size_t)(k0 + 8) * HE),
                                            __ldg(wc_n + (size_t)(k0 + 9) * HE));
            }
        }
    }

    // ===== Phase B: static half-b schedule u = cta + 148*i =====
    const float4* X4 = (const float4*)X;
    int u = blockIdx.x;

    // preload unit u into BUF0 (half = u&1 selects 128-row window of b = u>>1)
    if (u < UNITS) {
        #pragma unroll
        for (int g = 0; g < 2; g++) {
            const float4* src = X4 + (size_t)(u >> 1) * 4096
                                   + (u & 1) * 2048 + g * 1024;
            float4 v[4];
            #pragma unroll
            for (int j = 0; j < 4; j++) v[j] = src[tid + j * 256];
            cvt_sts_group(smem, S_BUF0 + g * 8192, tid, v);
        }
    }
    __syncthreads();

    int it = 0;
    #pragma unroll 1
    for (; u < UNITS; u += NCTA, it++) {
        const int nu = u + NCTA;
        const bool have_next = (nu < UNITS);
        const int bufoff  = (it & 1) ? S_BUF1 : S_BUF0;
        const int nbufoff = (it & 1) ? S_BUF0 : S_BUF1;
        float sacc0 = 0.0f, sacc1 = 0.0f;

        #pragma unroll
        for (int g = 0; g < 2; g++) {
            // ---- LDG group g of NEXT unit (latency hidden behind 4 m-tiles)
            float4 v[4];
            if (have_next) {
                const float4* nsrc = X4 + (size_t)(nu >> 1) * 4096
                                        + (nu & 1) * 2048 + g * 1024;
                #pragma unroll
                for (int j = 0; j < 4; j++) v[j] = nsrc[tid + j * 256];
            }

            // ---- 4 m-tiles of current unit (local rows (4g+mq)*16 ..)
            #pragma unroll
            for (int mq = 0; mq < 4; mq++) {
                const int m0 = (g * 4 + mq) * 16;
                float c[EE][4];
                #pragma unroll
                for (int e = 0; e < EE; e++)
                    #pragma unroll
                    for (int i = 0; i < 4; i++) c[e][i] = 0.0f;

                #pragma unroll
                for (int ks = 0; ks < 4; ks++) {
                    uint32_t off = (uint32_t)(m0 + (lane & 15)) * 128u
                                 + (uint32_t)ks * 32u + (uint32_t)(lane >> 4) * 16u;
                    uint32_t sw = swz(off);
                    uint32_t a0, a1, a2, a3;
                    ldsm_x4(sb + bufoff + sw, a0, a1, a2, a3);
                    #pragma unroll
                    for (int e = 0; e < EE; e++)
                        mma_fp16(c[e][0], c[e][1], c[e][2], c[e][3],
                                 a0, a1, a2, a3, bf[e][2 * ks], bf[e][2 * ks + 1]);
                }

                // max over E first (lrelu monotone -> commutes exactly)
                float v0 = c[0][0], v1 = c[0][1], v2 = c[0][2], v3 = c[0][3];
                #pragma unroll
                for (int e = 1; e < EE; e++) {
                    v0 = fmaxf(v0, c[e][0]);
                    v1 = fmaxf(v1, c[e][1]);
                    v2 = fmaxf(v2, c[e][2]);
                    v3 = fmaxf(v3, c[e][3]);
                }
                sacc0 += lrelu(v0) + lrelu(v2);   // col h = hb*8 + (lane%4)*2
                sacc1 += lrelu(v1) + lrelu(v3);   // col h+1
            }

            // ---- convert + store group g of next unit (nbuf retired by the
            //      previous end-of-unit barrier; no extra sync needed)
            if (have_next) cvt_sts_group(smem, nbufoff + g * 8192, tid, v);
        }

        // ---- flush pooled half partials: warp reduce -> g_part[u], fence
        #pragma unroll
        for (int o = 4; o <= 16; o <<= 1) {
            sacc0 += __shfl_xor_sync(0xffffffffu, sacc0, o);
            sacc1 += __shfl_xor_sync(0xffffffffu, sacc1, o);
        }
        if (lane < 4)
            *(float2*)&g_part[(size_t)u * HH + hb * 8 + lane * 2] =
                make_float2(sacc0, sacc1);
        __threadfence();   // release this warp's partials
        __syncthreads();   // all warps' fenced STGs done; rotate buffers

        // ---- non-blocking combine: warp 0 only (others roll into next unit)
        if (hb == 0) {
            const int b = u >> 1;
            int old = 0;
            if (lane == 0) old = atomicAdd(&g_cnt[b], 1);
            old = __shfl_sync(0xffffffffu, old, 0);
            if (old == 1) {            // second half arrived: combine + fc1
                __threadfence();       // acquire: other CTA's partials visible
                float2 p0 = *(const float2*)&g_part[(size_t)(2 * b) * HH + lane * 2];
                float2 p1 = *(const float2*)&g_part[(size_t)(2 * b + 1) * HH + lane * 2];
                float* tsm = (float*)(smem + S_TSM);   // warp-0 private
                tsm[lane * 2]     = p0.x + p1.x;       // fixed order: half0+half1
                tsm[lane * 2 + 1] = p0.y + p1.y;
                __syncwarp();
                const float* wfc = (const float*)(smem + S_WFC);
                float uacc = ((const float*)(smem + S_FB))[lane];
                #pragma unroll 8
                for (int h = 0; h < HH; h++)
                    uacc = fmaf(tsm[h], wfc[h * 32 + lane], uacc);
                g_u[b * 32 + lane] = uacc;
                if (lane == 0) g_cnt[b] = 0;   // self-reset for graph replay
            }
        }
    }

    // ===== Phase C: last CTA runs BatchNorm + LeakyReLU + fc2 inline =====
    __threadfence();
    if (tid == 0) {
        int old = atomicAdd(&g_done, 1);
        ctl[0] = (old == NCTA - 1) ? 1 : 0;
    }
    __syncthreads();
    if (!ctl[0]) return;

    // stage g_u into padded smem US[b][j] stride 33 (Phase B region is dead)
    float* US = (float*)smem;
    for (int i = tid; i < BB * 32; i += K1_THREADS)
        US[(i >> 5) * 33 + (i & 31)] = g_u[i];
    float* PS   = US + BB * 33;                  // [8][32] partials
    float* MEAN = PS + 256;                      // [32]
    float* RS   = MEAN + 32;                     // [32]
    __syncthreads();

    const int j = tid & 31, g = tid >> 5;        // 8 groups x 32 features
    {
        float s = 0.0f;
        #pragma unroll 8
        for (int bb = g * 64; bb < g * 64 + 64; bb++) s += US[bb * 33 + j];
        PS[g * 32 + j] = s;
    }
    __syncthreads();
    if (tid < 32) {
        float m = 0.0f;
        #pragma unroll
        for (int g2 = 0; g2 < 8; g2++) m += PS[g2 * 32 + tid];
        MEAN[tid] = m * (1.0f / (float)BB);
    }
    __syncthreads();
    {
        float mu = MEAN[j], s = 0.0f;
        #pragma unroll 8
        for (int bb = g * 64; bb < g * 64 + 64; bb++) {
            float d = US[bb * 33 + j] - mu;
            s += d * d;
        }
        PS[g * 32 + j] = s;
    }
    __syncthreads();
    if (tid < 32) {
        float v = 0.0f;
        #pragma unroll
        for (int g2 = 0; g2 < 8; g2++) v += PS[g2 * 32 + tid];
        RS[tid] = rsqrtf(v * (1.0f / (float)BB) + BN_EPS);
    }
    __syncthreads();

    for (int bb = tid; bb < BB; bb += K1_THREADS) {
        float a = __ldg(&fc2_b[0]);
        #pragma unroll
        for (int j2 = 0; j2 < 32; j2++) {
            float y = (US[bb * 33 + j2] - MEAN[j2]) * RS[j2] * __ldg(&gamma[j2]) + __ldg(&beta[j2]);
            a = fmaf(lrelu(y), __ldg(&fc2_w[j2]), a);
        }
        out[bb] = a;
    }

    // reset counter for next graph replay
    if (tid == 0) g_done = 0;
}

// ---------------------------------------------------------------------------
extern "C" void kernel_launch(void* const* d_in, const int* in_sizes, int n_in,
                              void* d_out, int out_size) {
    const float* X     = (const float*)d_in[0];
    const float* Wc    = (const float*)d_in[1];
    const float* fc1_w = (const float*)d_in[2];
    const float* fc1_b = (const float*)d_in[3];
    const float* gamma = (const float*)d_in[4];
    const float* beta  = (const float*)d_in[5];
    const float* fc2_w = (const float*)d_in[6];
    const float* fc2_b = (const float*)d_in[7];
    float* out = (float*)d_out;

    cudaFuncSetAttribute(fused_all, cudaFuncAttributeMaxDynamicSharedMemorySize, SM_TOTAL);
    fused_all<<<NCTA, K1_THREADS, SM_TOTAL>>>(X, Wc, fc1_w, fc1_b,
                                              gamma, beta, fc2_w, fc2_b, out);
}

// round 17
// speedup vs baseline: 1.0960x; 1.0960x over previous
#include <cuda_runtime.h>
#include <cuda_fp16.h>
#include <cstdint>

// ---------------------------------------------------------------------------
// Problem constants
// ---------------------------------------------------------------------------
#define BB 512      // batch
#define SS 256      // set size
#define DD 64       // feature dim (K)
#define HH 64       // n_hidden_sets
#define EE 8        // n_elements
#define HE 512      // H*E (N of GEMM)
#define BN_EPS 1e-5f

#define NCTA 148          // 1 CTA per SM (forced via smem)
#define K1_THREADS 256
#define UNITS 1024        // 512 b x 2 halves (128 rows each)

// smem layout (bytes) — Phase C US overlays [0, ~69K) after Phase B retires
#define S_BUF0 0                    // X fp16 half-b buf 0 (16 KB)
#define S_BUF1 16384                // X fp16 half-b buf 1 (16 KB)
#define S_WFC  32768                // fc1_w transposed [h][j] (8 KB)
#define S_FB   40960                // fc1_b [32]
#define S_TSM  41088                // 2 x 64 floats (parity staging)
#define S_CTL  69632                // control ints (outside Phase C's US+PS)
// Request 120 KB so 2 CTAs cannot co-reside on one SM.
#define SM_TOTAL 122880

// ---------------------------------------------------------------------------
// Device scratch (no dynamic allocation allowed)
// ---------------------------------------------------------------------------
__device__ float g_part[UNITS * HH];   // boundary-split half partial sums
__device__ int   g_cnt[BB];            // split-b arrival counters (self-reset)
__device__ float g_u[BB * 32];         // fc1 output
__device__ int   g_done = 0;           // CTA completion counter

__device__ __forceinline__ uint32_t smem_u32(const void* p) {
    uint32_t a;
    asm("{ .reg .u64 t; cvta.to.shared.u64 t, %1; cvt.u32.u64 %0, t; }" : "=r"(a) : "l"(p));
    return a;
}
__device__ __forceinline__ uint32_t swz(uint32_t off) {   // SW128: conflict-free ldmatrix
    return off ^ ((off >> 3) & 0x70);
}
__device__ __forceinline__ float lrelu(float x) { return fmaxf(x, 0.01f * x); }

__device__ __forceinline__ void ldsm_x4(uint32_t addr, uint32_t& r0, uint32_t& r1,
                                        uint32_t& r2, uint32_t& r3) {
    asm volatile("ldmatrix.sync.aligned.m8n8.x4.shared.b16 {%0,%1,%2,%3}, [%4];"
                 : "=r"(r0), "=r"(r1), "=r"(r2), "=r"(r3) : "r"(addr));
}
__device__ __forceinline__ void mma_fp16(float& c0, float& c1, float& c2, float& c3,
                                         uint32_t a0, uint32_t a1, uint32_t a2, uint32_t a3,
                                         uint32_t b0, uint32_t b1) {
    asm volatile("mma.sync.aligned.m16n8k16.row.col.f32.f16.f16.f32 "
                 "{%0,%1,%2,%3}, {%4,%5,%6,%7}, {%8,%9}, {%0,%1,%2,%3};"
                 : "+f"(c0), "+f"(c1), "+f"(c2), "+f"(c3)
                 : "r"(a0), "r"(a1), "r"(a2), "r"(a3), "r"(b0), "r"(b1));
}
__device__ __forceinline__ uint32_t pack_h2(float lo, float hi) {
    __half2 h = __floats2half2_rn(lo, hi);
    return *(uint32_t*)&h;
}

// convert 4 float4 (one 64-row group's share) -> swizzled fp16 at bufoff
__device__ __forceinline__ void cvt_sts_group(char* smem, int bufoff, int tid,
                                              const float4* v) {
    #pragma unroll
    for (int j = 0; j < 4; j++) {
        int cc = tid + j * 256;            // float4 idx within 64-row group
        int row = cc >> 4, k4 = (cc & 15) << 2;
        uint32_t sw = swz((uint32_t)row * 128u + (uint32_t)k4 * 2u);
        *(uint2*)(smem + bufoff + sw) =
            make_uint2(pack_h2(v[j].x, v[j].y), pack_h2(v[j].z, v[j].w));
    }
}

// ---------------------------------------------------------------------------
// Single persistent kernel: 1 CTA/SM, blocked half-b partition (6-7 units/CTA),
// interior b's fully local (R15-identical math); only boundary b's use the
// global combine protocol.
// ---------------------------------------------------------------------------
__global__ __launch_bounds__(K1_THREADS, 1)
void fused_all(const float* __restrict__ X, const float* __restrict__ Wc,
               const float* __restrict__ fc1_w, const float* __restrict__ fc1_b,
               const float* __restrict__ gamma, const float* __restrict__ beta,
               const float* __restrict__ fc2_w, const float* __restrict__ fc2_b,
               float* __restrict__ out) {
    extern __shared__ char smem[];
    const uint32_t sb = smem_u32(smem);
    const int tid  = threadIdx.x;
    const int hb   = tid >> 5;        // warp id == h-block
    const int lane = tid & 31;
    int* ctl = (int*)(smem + S_CTL);  // [0]=last-CTA flag

    // ===== Phase A: stage fc1 weights/bias; B fragments direct from Wc =====
    for (int i = tid; i < 32 * HH; i += K1_THREADS) {
        int j = i >> 6, h = i & 63;
        ((float*)(smem + S_WFC))[h * 32 + j] = fc1_w[i];
    }
    if (tid < 32) ((float*)(smem + S_FB))[tid] = fc1_b[tid];

    // PTX m16n8k16 .col B mapping (bit-exact verified R11-R16)
    uint32_t bf[EE][8];
    {
        const int n  = hb * 8 + (lane >> 2);
        const int kb = (lane & 3) * 2;
        #pragma unroll
        for (int e = 0; e < EE; e++) {
            const float* wc_n = Wc + e * 64 + n;
            #pragma unroll
            for (int ks = 0; ks < 4; ks++) {
                int k0 = ks * 16 + kb;
                bf[e][2 * ks]     = pack_h2(__ldg(wc_n + (size_t)k0 * HE),
                                            __ldg(wc_n + (size_t)(k0 + 1) * HE));
                bf[e][2 * ks + 1] = pack_h2(__ldg(wc_n + (size_t)(k0 + 8) * HE),
                                            __ldg(wc_n + (size_t)(k0 + 9) * HE));
            }
        }
    }

    // ===== Phase B: blocked unit range [u0, u1) =====
    const int u0 = (int)(((long long)blockIdx.x * UNITS) / NCTA);
    const int u1 = (int)(((long long)(blockIdx.x + 1) * UNITS) / NCTA);
    const float4* X4 = (const float4*)X;

    // preload unit u0 into BUF0 (unit u covers rows [(u&1)*128, +128) of b=u>>1)
    #pragma unroll
    for (int g = 0; g < 2; g++) {
        const float4* src = X4 + (size_t)(u0 >> 1) * 4096 + (u0 & 1) * 2048 + g * 1024;
        float4 v[4];
        #pragma unroll
        for (int j = 0; j < 4; j++) v[j] = src[tid + j * 256];
        cvt_sts_group(smem, S_BUF0 + g * 8192, tid, v);
    }
    __syncthreads();

    float sacc0 = 0.0f, sacc1 = 0.0f;
    int it = 0;
    #pragma unroll 1
    for (int u = u0; u < u1; u++, it++) {
        const int b = u >> 1;
        const bool have_next = (u + 1 < u1);
        const int bufoff  = (it & 1) ? S_BUF1 : S_BUF0;
        const int nbufoff = (it & 1) ? S_BUF0 : S_BUF1;

        #pragma unroll
        for (int g = 0; g < 2; g++) {
            // ---- LDG group g of NEXT unit (latency hidden behind 4 m-tiles)
            float4 v[4];
            if (have_next) {
                const float4* nsrc = X4 + (size_t)((u + 1) >> 1) * 4096
                                        + ((u + 1) & 1) * 2048 + g * 1024;
                #pragma unroll
                for (int j = 0; j < 4; j++) v[j] = nsrc[tid + j * 256];
            }

            // ---- 4 m-tiles of current unit (local rows (4g+mq)*16 ..)
            #pragma unroll
            for (int mq = 0; mq < 4; mq++) {
                const int m0 = (g * 4 + mq) * 16;
                float c[EE][4];
                #pragma unroll
                for (int e = 0; e < EE; e++)
                    #pragma unroll
                    for (int i = 0; i < 4; i++) c[e][i] = 0.0f;

                #pragma unroll
                for (int ks = 0; ks < 4; ks++) {
                    uint32_t off = (uint32_t)(m0 + (lane & 15)) * 128u
                                 + (uint32_t)ks * 32u + (uint32_t)(lane >> 4) * 16u;
                    uint32_t sw = swz(off);
                    uint32_t a0, a1, a2, a3;
                    ldsm_x4(sb + bufoff + sw, a0, a1, a2, a3);
                    #pragma unroll
                    for (int e = 0; e < EE; e++)
                        mma_fp16(c[e][0], c[e][1], c[e][2], c[e][3],
                                 a0, a1, a2, a3, bf[e][2 * ks], bf[e][2 * ks + 1]);
                }

                // max over E first (lrelu monotone -> commutes exactly)
                float v0 = c[0][0], v1 = c[0][1], v2 = c[0][2], v3 = c[0][3];
                #pragma unroll
                for (int e = 1; e < EE; e++) {
                    v0 = fmaxf(v0, c[e][0]);
                    v1 = fmaxf(v1, c[e][1]);
                    v2 = fmaxf(v2, c[e][2]);
                    v3 = fmaxf(v3, c[e][3]);
                }
                sacc0 += lrelu(v0) + lrelu(v2);   // col h = hb*8 + (lane%4)*2
                sacc1 += lrelu(v1) + lrelu(v3);   // col h+1
            }

            // ---- convert + store group g of next unit (nbuf retired by the
            //      previous end-of-unit barrier)
            if (have_next) cvt_sts_group(smem, nbufoff + g * 8192, tid, v);
        }

        // is this the last unit of b that THIS CTA owns?
        const bool last_of_b = (u == 2 * b + 1) || (u + 1 == u1);
        const bool full_b    = (u == 2 * b + 1) && (2 * b >= u0);

        if (last_of_b) {
            #pragma unroll
            for (int o = 4; o <= 16; o <<= 1) {
                sacc0 += __shfl_xor_sync(0xffffffffu, sacc0, o);
                sacc1 += __shfl_xor_sync(0xffffffffu, sacc1, o);
            }
            if (full_b) {
                // interior b: purely local (identical math to R15)
                if (lane < 4) {
                    float* tsm = (float*)(smem + S_TSM) + (it & 1) * HH;
                    tsm[hb * 8 + lane * 2]     = sacc0;
                    tsm[hb * 8 + lane * 2 + 1] = sacc1;
                }
            } else {
                // boundary half: publish to g_part (rare: <=2 per CTA total)
                if (lane < 4)
                    *(float2*)&g_part[(size_t)u * HH + hb * 8 + lane * 2] =
                        make_float2(sacc0, sacc1);
                __threadfence();
            }
            sacc0 = 0.0f; sacc1 = 0.0f;
        }
        __syncthreads();   // buffer rotation (and orders boundary STGs)

        if (last_of_b) {
            if (full_b) {
                // local fc1 (warp 0 only; other warps roll into next unit)
                if (tid < 32) {
                    const float* tsm = (const float*)(smem + S_TSM) + (it & 1) * HH;
                    const float* wfc = (const float*)(smem + S_WFC);
                    float uacc = ((const float*)(smem + S_FB))[tid];
                    #pragma unroll 8
                    for (int h = 0; h < HH; h++)
                        uacc = fmaf(tsm[h], wfc[h * 32 + tid], uacc);
                    g_u[b * 32 + tid] = uacc;
                }
            } else if (hb == 0) {
                // split b: second-arriving CTA combines (fixed half0+half1 order)
                int old = 0;
                if (lane == 0) old = atomicAdd(&g_cnt[b], 1);
                old = __shfl_sync(0xffffffffu, old, 0);
                if (old == 1) {
                    __threadfence();   // acquire other CTA's partial
                    float2 p0 = *(const float2*)&g_part[(size_t)(2 * b) * HH + lane * 2];
                    float2 p1 = *(const float2*)&g_part[(size_t)(2 * b + 1) * HH + lane * 2];
                    float* tsm = (float*)(smem + S_TSM) + (it & 1) * HH;
                    tsm[lane * 2]     = p0.x + p1.x;
                    tsm[lane * 2 + 1] = p0.y + p1.y;
                    __syncwarp();
                    const float* wfc = (const float*)(smem + S_WFC);
                    float uacc = ((const float*)(smem + S_FB))[lane];
                    #pragma unroll 8
                    for (int h = 0; h < HH; h++)
                        uacc = fmaf(tsm[h], wfc[h * 32 + lane], uacc);
                    g_u[b * 32 + lane] = uacc;
                    if (lane == 0) g_cnt[b] = 0;   // self-reset for graph replay
                }
            }
        }
    }

    // ===== Phase C: last CTA runs BatchNorm + LeakyReLU + fc2 inline =====
    __threadfence();
    if (tid == 0) {
        int old = atomicAdd(&g_done, 1);
        ctl[0] = (old == NCTA - 1) ? 1 : 0;
    }
    __syncthreads();
    if (!ctl[0]) return;

    // stage g_u into padded smem US[b][j] stride 33 (Phase B region is dead)
    float* US = (float*)smem;
    for (int i = tid; i < BB * 32; i += K1_THREADS)
        US[(i >> 5) * 33 + (i & 31)] = g_u[i];
    float* PS   = US + BB * 33;                  // [8][32] partials
    float* MEAN = PS + 256;                      // [32]
    float* RS   = MEAN + 32;                     // [32]
    __syncthreads();

    const int j = tid & 31, g = tid >> 5;        // 8 groups x 32 features
    {
        float s = 0.0f;
        #pragma unroll 8
        for (int bb = g * 64; bb < g * 64 + 64; bb++) s += US[bb * 33 + j];
        PS[g * 32 + j] = s;
    }
    __syncthreads();
    if (tid < 32) {
        float m = 0.0f;
        #pragma unroll
        for (int g2 = 0; g2 < 8; g2++) m += PS[g2 * 32 + tid];
        MEAN[tid] = m * (1.0f / (float)BB);
    }
    __syncthreads();
    {
        float mu = MEAN[j], s = 0.0f;
        #pragma unroll 8
        for (int bb = g * 64; bb < g * 64 + 64; bb++) {
            float d = US[bb * 33 + j] - mu;
            s += d * d;
        }
        PS[g * 32 + j] = s;
    }
    __syncthreads();
    if (tid < 32) {
        float v = 0.0f;
        #pragma unroll
        for (int g2 = 0; g2 < 8; g2++) v += PS[g2 * 32 + tid];
        RS[tid] = rsqrtf(v * (1.0f / (float)BB) + BN_EPS);
    }
    __syncthreads();

    for (int bb = tid; bb < BB; bb += K1_THREADS) {
        float a = __ldg(&fc2_b[0]);
        #pragma unroll
        for (int j2 = 0; j2 < 32; j2++) {
            float y = (US[bb * 33 + j2] - MEAN[j2]) * RS[j2] * __ldg(&gamma[j2]) + __ldg(&beta[j2]);
            a = fmaf(lrelu(y), __ldg(&fc2_w[j2]), a);
        }
        out[bb] = a;
    }

    // reset counter for next graph replay
    if (tid == 0) g_done = 0;
}

// ---------------------------------------------------------------------------
extern "C" void kernel_launch(void* const* d_in, const int* in_sizes, int n_in,
                              void* d_out, int out_size) {
    const float* X     = (const float*)d_in[0];
    const float* Wc    = (const float*)d_in[1];
    const float* fc1_w = (const float*)d_in[2];
    const float* fc1_b = (const float*)d_in[3];
    const float* gamma = (const float*)d_in[4];
    const float* beta  = (const float*)d_in[5];
    const float* fc2_w = (const float*)d_in[6];
    const float* fc2_b = (const float*)d_in[7];
    float* out = (float*)d_out;

    cudaFuncSetAttribute(fused_all, cudaFuncAttributeMaxDynamicSharedMemorySize, SM_TOTAL);
    fused_all<<<NCTA, K1_THREADS, SM_TOTAL>>>(X, Wc, fc1_w, fc1_b,
                                              gamma, beta, fc2_w, fc2_b, out);
}